// round 10
// baseline (speedup 1.0000x reference)
#include <cuda_runtime.h>
#include <cuda_bf16.h>
#include <cuda_fp16.h>
#include <math.h>
#include <stdint.h>

// ----------------------------------------------------------------------------
// Transformer forward: 6 layers, B=4, N=1024, D=1024, H=16, hd=64, MLP=4096
// Round 10: dense GEMMs retiled to 128x64 CTAs, 2 CTAs/SM (wave-quantization
// + epilogue overlap). Numerics identical to R9 (single-product fp16).
// ----------------------------------------------------------------------------

static constexpr int BATCH  = 4;
static constexpr int SEQ    = 1024;
static constexpr int DIM    = 1024;
static constexpr int HEADS  = 16;
static constexpr int HD     = 64;
static constexpr int MLPD   = 4096;
static constexpr int DEPTH  = 6;
static constexpr int TOK    = BATCH * SEQ;          // 4096
static constexpr float EPS  = 1e-5f;
static constexpr float SCALE = 0.03125f;            // DIM^-0.5

// ---------------- scratch (device globals; no allocation) -------------------
__device__ float  g_x [(size_t)TOK * DIM];
__device__ __half g_y [(size_t)TOK * DIM];   // LN out
__device__ __half g_q [(size_t)TOK * DIM];   // [bh][n][64]
__device__ __half g_k [(size_t)TOK * DIM];
__device__ __half g_v [(size_t)TOK * DIM];
__device__ __half g_a [(size_t)TOK * DIM];   // attn out [tok][DIM]
__device__ __half g_h [(size_t)TOK * MLPD];  // MLP hidden

// transposed fp16 weights
__device__ __half g_wq[(size_t)DEPTH * 3 * DIM * DIM];
__device__ __half g_wp[(size_t)DEPTH * DIM * DIM];
__device__ __half g_w1[(size_t)DEPTH * MLPD * DIM];
__device__ __half g_w2[(size_t)DEPTH * DIM * MLPD];

// ---------------------------- PTX helpers -----------------------------------
__device__ __forceinline__ uint32_t smem_u32(const void* p) {
    uint32_t a;
    asm("{ .reg .u64 t; cvta.to.shared.u64 t, %1; cvt.u32.u64 %0, t; }"
        : "=r"(a) : "l"(p));
    return a;
}

__device__ __forceinline__ void ldsm4(uint32_t* r, uint32_t a) {
    asm volatile("ldmatrix.sync.aligned.m8n8.x4.shared.b16 {%0,%1,%2,%3}, [%4];"
        : "=r"(r[0]), "=r"(r[1]), "=r"(r[2]), "=r"(r[3]) : "r"(a));
}
__device__ __forceinline__ void ldsm4t(uint32_t* r, uint32_t a) {
    asm volatile("ldmatrix.sync.aligned.m8n8.x4.trans.shared.b16 {%0,%1,%2,%3}, [%4];"
        : "=r"(r[0]), "=r"(r[1]), "=r"(r[2]), "=r"(r[3]) : "r"(a));
}

__device__ __forceinline__ void mma_h(float* c, const uint32_t* a,
                                      uint32_t b0, uint32_t b1) {
    asm volatile("mma.sync.aligned.m16n8k16.row.col.f32.f16.f16.f32 "
        "{%0,%1,%2,%3}, {%4,%5,%6,%7}, {%8,%9}, {%0,%1,%2,%3};"
        : "+f"(c[0]), "+f"(c[1]), "+f"(c[2]), "+f"(c[3])
        : "r"(a[0]), "r"(a[1]), "r"(a[2]), "r"(a[3]), "r"(b0), "r"(b1));
}

#define CP_ASYNC16(saddr, gptr) \
    asm volatile("cp.async.cg.shared.global [%0], [%1], 16;" :: "r"(saddr), "l"(gptr))
#define CP_COMMIT() asm volatile("cp.async.commit_group;" ::: "memory")
#define CP_WAIT(n)  asm volatile("cp.async.wait_group %0;" :: "n"(n) : "memory")

__device__ __forceinline__ uint32_t packh2(float x, float y) {
    __half2 p = __floats2half2_rn(x, y);
    return *(uint32_t*)&p;
}

// ----------------------------------------------------------------------------
// Weight transpose to fp16: W [L,K,N] fp32 -> Wt [L,N,K] fp16
__global__ void wconvert(const float* __restrict__ W, __half* __restrict__ Th,
                         int K, int N) {
    __shared__ float t[32][33];
    size_t loff = (size_t)blockIdx.z * K * N;
    const float* Wl = W + loff;
    int n0 = blockIdx.x * 32, k0 = blockIdx.y * 32;
    #pragma unroll
    for (int i = 0; i < 4; i++) {
        int k = k0 + threadIdx.y + i * 8;
        t[threadIdx.y + i * 8][threadIdx.x] = Wl[(size_t)k * N + n0 + threadIdx.x];
    }
    __syncthreads();
    #pragma unroll
    for (int i = 0; i < 4; i++) {
        int n = n0 + threadIdx.y + i * 8;
        float v = t[threadIdx.x][threadIdx.y + i * 8];
        Th[loff + (size_t)n * K + k0 + threadIdx.x] = __float2half_rn(v);
    }
}

// ----------------------------------------------------------------------------
// LayerNorm: warp per row, one pass (sum + sumsq), fp16 output.
__global__ void ln_half(const float* __restrict__ x,
                        const float* __restrict__ w,
                        const float* __restrict__ b,
                        __half* __restrict__ y) {
    int row = blockIdx.x * 8 + (threadIdx.x >> 5);
    int lane = threadIdx.x & 31;
    const float4* xr = (const float4*)(x + (size_t)row * DIM);
    const float4* w4 = (const float4*)w;
    const float4* b4 = (const float4*)b;

    float4 v[8];
    float s = 0.f, s2 = 0.f;
    #pragma unroll
    for (int i = 0; i < 8; i++) {
        v[i] = xr[lane + i * 32];
        s  += v[i].x + v[i].y + v[i].z + v[i].w;
        s2 += v[i].x * v[i].x + v[i].y * v[i].y + v[i].z * v[i].z + v[i].w * v[i].w;
    }
    #pragma unroll
    for (int o = 16; o > 0; o >>= 1) {
        s  += __shfl_xor_sync(0xffffffffu, s,  o);
        s2 += __shfl_xor_sync(0xffffffffu, s2, o);
    }
    float mu = s * (1.0f / DIM);
    float var = s2 * (1.0f / DIM) - mu * mu;
    float rstd = rsqrtf(var + EPS);

    __half* yr = y + (size_t)row * DIM;
    #pragma unroll
    for (int i = 0; i < 8; i++) {
        int idx = (lane + i * 32);
        float4 wv = w4[idx], bv = b4[idx];
        float g0 = (v[i].x - mu) * rstd * wv.x + bv.x;
        float g1 = (v[i].y - mu) * rstd * wv.y + bv.y;
        float g2 = (v[i].z - mu) * rstd * wv.z + bv.z;
        float g3 = (v[i].w - mu) * rstd * wv.w + bv.w;
        uint2 pk;
        pk.x = packh2(g0, g1);
        pk.y = packh2(g2, g3);
        *(uint2*)(yr + idx * 4) = pk;
    }
}

// ----------------------------------------------------------------------------
// Dense GEMM, single-product fp16: C = A @ B (fp32 accum)
// CTA tile 128x64, BK=32, 8 warps (2m x 4n), warp tile 64x16, 2 CTAs/SM.
// EPI: 2 = +bias,gelu -> fp16 Ch;  3 = +bias+res -> fp32 Cf;
//      4 = +bias -> scatter fp16 QKV (per-head layout)
template<int EPI>
__global__ void __launch_bounds__(256, 2)
gemm_mma(const __half* __restrict__ A, const __half* __restrict__ B,
         const float* __restrict__ bias, const float* __restrict__ res,
         float* __restrict__ Cf, __half* __restrict__ Ch,
         __half* __restrict__ Qp, __half* __restrict__ Kp, __half* __restrict__ Vp,
         int M, int N, int K) {
    constexpr int STAGES = 3;
    constexpr int ROWB   = 80;             // padded row stride (32 fp16 + 16B)
    constexpr int ATILE  = 128 * ROWB;     // 10240 B
    constexpr int BTILE  = 64 * ROWB;      // 5120 B
    constexpr int STAGEB = ATILE + BTILE;  // 15360 B per stage

    extern __shared__ char smem[];
    uint32_t sb = smem_u32(smem);
    int tid = threadIdx.x, lane = tid & 31, wid = tid >> 5;
    int bm = blockIdx.y * 128, bn = blockIdx.x * 64;
    int warp_m = wid >> 2, warp_n = wid & 3;     // 2 x 4

    const __half* Asrc = A + (size_t)bm * K;
    const __half* Bsrc = B + (size_t)bn * K;
    int nch = K >> 5;

    int g = lane >> 3;
    uint32_t rowsel = (uint32_t)(((g & 1) << 3) + (lane & 7));
    uint32_t colsel = (uint32_t)((g >> 1) * 16);

    float acc[4][2][4];
    #pragma unroll
    for (int i = 0; i < 4; i++)
        #pragma unroll
        for (int j = 0; j < 2; j++)
            #pragma unroll
            for (int q = 0; q < 4; q++) acc[i][j][q] = 0.f;

    // 768 x 16B chunks per stage (A: 512, B: 256) -> 3 per thread
    auto issue = [&](int ch) {
        int k0 = ch << 5;
        uint32_t sbase = sb + (uint32_t)(ch % STAGES) * STAGEB;
        #pragma unroll
        for (int j = 0; j < 3; j++) {
            int c2 = j * 256 + tid;               // 0..767
            if (c2 < 512) {
                int row = c2 >> 2, ck = c2 & 3;
                CP_ASYNC16(sbase + (uint32_t)(row * ROWB + ck * 16),
                           Asrc + (size_t)row * K + k0 + ck * 8);
            } else {
                int idx = c2 - 512, row = idx >> 2, ck = idx & 3;
                CP_ASYNC16(sbase + (uint32_t)(ATILE + row * ROWB + ck * 16),
                           Bsrc + (size_t)row * K + k0 + ck * 8);
            }
        }
    };

    #pragma unroll
    for (int s = 0; s < STAGES; s++) { issue(s); CP_COMMIT(); }

    for (int c = 0; c < nch; c++) {
        CP_WAIT(STAGES - 1);
        __syncthreads();
        uint32_t st = sb + (uint32_t)((c % STAGES) * STAGEB);

        #pragma unroll
        for (int kh2 = 0; kh2 < 2; kh2++) {
            uint32_t kb = (uint32_t)(kh2 * 32) + colsel;
            uint32_t af[4][4], bf[4];
            #pragma unroll
            for (int mi = 0; mi < 4; mi++) {
                uint32_t r = (uint32_t)(warp_m * 64 + mi * 16) + rowsel;
                ldsm4(af[mi], st + r * ROWB + kb);
            }
            {
                uint32_t r = (uint32_t)(warp_n * 16) + rowsel;
                ldsm4(bf, st + ATILE + r * ROWB + kb);
            }
            #pragma unroll
            for (int mi = 0; mi < 4; mi++)
                #pragma unroll
                for (int nj = 0; nj < 2; nj++)
                    mma_h(acc[mi][nj], af[mi], bf[nj], bf[nj + 2]);
        }
        __syncthreads();
        if (c + STAGES < nch) issue(c + STAGES);
        CP_COMMIT();
    }

    // ---- epilogue ----
    #pragma unroll
    for (int mi = 0; mi < 4; mi++) {
        int r0 = bm + warp_m * 64 + mi * 16 + (lane >> 2);
        #pragma unroll
        for (int nj = 0; nj < 2; nj++) {
            int cc = bn + warp_n * 16 + nj * 8 + (lane & 3) * 2;
            float b0 = bias[cc], b1 = bias[cc + 1];
            #pragma unroll
            for (int half = 0; half < 2; half++) {
                int r = r0 + half * 8;
                float v0 = acc[mi][nj][half * 2 + 0] + b0;
                float v1 = acc[mi][nj][half * 2 + 1] + b1;
                if (EPI == 2) {
                    size_t o = (size_t)r * N + cc;
                    v0 = 0.5f * v0 * (1.0f + erff(v0 * 0.70710678118654752f));
                    v1 = 0.5f * v1 * (1.0f + erff(v1 * 0.70710678118654752f));
                    *(uint32_t*)(Ch + o) = packh2(v0, v1);
                } else if (EPI == 3) {
                    size_t o = (size_t)r * N + cc;
                    v0 += res[o];
                    v1 += res[o + 1];
                    float2 f2; f2.x = v0; f2.y = v1;
                    *(float2*)(Cf + o) = f2;
                } else {  // EPI == 4: scatter qkv -> per-head fp16 layout
                    int sel = cc >> 10, hh = (cc >> 6) & 15, d = cc & 63;
                    int bb = r >> 10, nn = r & 1023;
                    size_t o = ((size_t)((bb << 4) + hh) * SEQ + nn) * 64 + d;
                    __half* dh = (sel == 0) ? Qp : (sel == 1) ? Kp : Vp;
                    *(uint32_t*)(dh + o) = packh2(v0, v1);
                }
            }
        }
    }
}

// ----------------------------------------------------------------------------
// Fused flash attention, single-product fp16 (unchanged from R9).
__global__ void __launch_bounds__(256, 1)
flash_kernel(const __half* __restrict__ Q, const __half* __restrict__ K,
             const __half* __restrict__ V, __half* __restrict__ O) {
    constexpr int RSTR   = 144;
    constexpr int KVT    = 64 * RSTR;
    constexpr int STAGEB = 2 * KVT;
    constexpr int QB     = 128 * RSTR;

    extern __shared__ char smem[];
    uint32_t sb = smem_u32(smem);
    int tid = threadIdx.x, lane = tid & 31, wid = tid >> 5;
    int bh = blockIdx.y, i0 = blockIdx.x * 128;
    size_t seqb = (size_t)bh * SEQ * 64;

    {
        const __half* qsrc = Q + seqb + (size_t)i0 * 64;
        #pragma unroll
        for (int j = 0; j < 4; j++) {
            int idx = j * 256 + tid;
            int row = idx >> 3, ck = idx & 7;
            CP_ASYNC16(sb + (uint32_t)(row * RSTR + ck * 16),
                       qsrc + (size_t)row * 64 + ck * 8);
        }
        CP_COMMIT();
    }
    const __half* kvs[2] = { K + seqb, V + seqb };
    auto issueKV = [&](int it) {
        int k0 = it * 64;
        uint32_t base = sb + QB + (uint32_t)(it & 1) * STAGEB;
        #pragma unroll
        for (int j = 0; j < 4; j++) {
            int idx = j * 256 + tid;
            int op = idx >> 9, rem = idx & 511, row = rem >> 3, ck = rem & 7;
            CP_ASYNC16(base + (uint32_t)(op * KVT + row * RSTR + ck * 16),
                       kvs[op] + (size_t)(k0 + row) * 64 + ck * 8);
        }
    };
    issueKV(0); CP_COMMIT();
    issueKV(1); CP_COMMIT();

    int g = lane >> 3;
    uint32_t lrow = (uint32_t)(((g & 1) << 3) + (lane & 7));
    uint32_t lcol = (uint32_t)((g >> 1) * 16);

    CP_WAIT(2);
    __syncthreads();
    uint32_t qf[4][4];
    {
        int r0 = wid * 16;
        #pragma unroll
        for (int c = 0; c < 4; c++)
            ldsm4(qf[c], sb + (uint32_t)((r0 + lrow) * RSTR + c * 32) + lcol);
    }

    float m0 = -1e30f, m1 = -1e30f, l0 = 0.f, l1 = 0.f;
    float o[8][4];
    #pragma unroll
    for (int nb = 0; nb < 8; nb++)
        #pragma unroll
        for (int q = 0; q < 4; q++) o[nb][q] = 0.f;

    for (int it = 0; it < 16; it++) {
        CP_WAIT(1);
        __syncthreads();
        uint32_t st = sb + QB + (uint32_t)(it & 1) * STAGEB;

        float s[8][4];
        #pragma unroll
        for (int nb = 0; nb < 8; nb++)
            #pragma unroll
            for (int q = 0; q < 4; q++) s[nb][q] = 0.f;

        #pragma unroll
        for (int c = 0; c < 4; c++) {
            uint32_t kf[4][4];
            #pragma unroll
            for (int p = 0; p < 4; p++)
                ldsm4(kf[p], st + (uint32_t)((p * 16 + lrow) * RSTR + c * 32) + lcol);
            #pragma unroll
            for (int p = 0; p < 4; p++) {
                mma_h(s[2 * p],     qf[c], kf[p][0], kf[p][2]);
                mma_h(s[2 * p + 1], qf[c], kf[p][1], kf[p][3]);
            }
        }

        float rm0 = -1e30f, rm1 = -1e30f;
        #pragma unroll
        for (int nb = 0; nb < 8; nb++) {
            #pragma unroll
            for (int q = 0; q < 4; q++) s[nb][q] *= SCALE;
            rm0 = fmaxf(rm0, fmaxf(s[nb][0], s[nb][1]));
            rm1 = fmaxf(rm1, fmaxf(s[nb][2], s[nb][3]));
        }
        rm0 = fmaxf(rm0, __shfl_xor_sync(0xffffffffu, rm0, 1));
        rm0 = fmaxf(rm0, __shfl_xor_sync(0xffffffffu, rm0, 2));
        rm1 = fmaxf(rm1, __shfl_xor_sync(0xffffffffu, rm1, 1));
        rm1 = fmaxf(rm1, __shfl_xor_sync(0xffffffffu, rm1, 2));
        float nm0 = fmaxf(m0, rm0), nm1 = fmaxf(m1, rm1);
        float a0 = __expf(m0 - nm0), a1 = __expf(m1 - nm1);
        m0 = nm0; m1 = nm1;

        float sum0 = 0.f, sum1 = 0.f;
        uint32_t pf[4][4];
        #pragma unroll
        for (int nb = 0; nb < 8; nb++) {
            float p00 = __expf(s[nb][0] - nm0);
            float p01 = __expf(s[nb][1] - nm0);
            float p10 = __expf(s[nb][2] - nm1);
            float p11 = __expf(s[nb][3] - nm1);
            sum0 += p00 + p01;
            sum1 += p10 + p11;
            int c = nb >> 1, off = (nb & 1) ? 2 : 0;
            pf[c][off + 0] = packh2(p00, p01);
            pf[c][off + 1] = packh2(p10, p11);
        }
        sum0 += __shfl_xor_sync(0xffffffffu, sum0, 1);
        sum0 += __shfl_xor_sync(0xffffffffu, sum0, 2);
        sum1 += __shfl_xor_sync(0xffffffffu, sum1, 1);
        sum1 += __shfl_xor_sync(0xffffffffu, sum1, 2);
        l0 = l0 * a0 + sum0;
        l1 = l1 * a1 + sum1;
        #pragma unroll
        for (int nb = 0; nb < 8; nb++) {
            o[nb][0] *= a0; o[nb][1] *= a0;
            o[nb][2] *= a1; o[nb][3] *= a1;
        }

        #pragma unroll
        for (int c = 0; c < 4; c++) {
            uint32_t vf[4][4];
            #pragma unroll
            for (int dp = 0; dp < 4; dp++)
                ldsm4t(vf[dp], st + KVT + (uint32_t)((c * 16 + lrow) * RSTR + dp * 32) + lcol);
            #pragma unroll
            for (int dp = 0; dp < 4; dp++) {
                mma_h(o[2 * dp],     pf[c], vf[dp][0], vf[dp][1]);
                mma_h(o[2 * dp + 1], pf[c], vf[dp][2], vf[dp][3]);
            }
        }
        __syncthreads();
        if (it + 2 < 16) issueKV(it + 2);
        CP_COMMIT();
    }

    float inv0 = 1.0f / l0, inv1 = 1.0f / l1;
    int b = bh >> 4, h = bh & 15;
    int nrow = i0 + wid * 16 + (lane >> 2);
    size_t t0 = (size_t)b * SEQ + nrow;
    #pragma unroll
    for (int nb = 0; nb < 8; nb++) {
        int col = h * 64 + nb * 8 + (lane & 3) * 2;
        *(uint32_t*)(O + t0 * DIM + col)       = packh2(o[nb][0] * inv0, o[nb][1] * inv0);
        *(uint32_t*)(O + (t0 + 8) * DIM + col) = packh2(o[nb][2] * inv1, o[nb][3] * inv1);
    }
}

// ----------------------------------------------------------------------------
extern "C" void kernel_launch(void* const* d_in, const int* in_sizes, int n_in,
                              void* d_out, int out_size) {
    const float* x_in   = (const float*)d_in[0];
    const float* ln1_w  = (const float*)d_in[1];
    const float* ln1_b  = (const float*)d_in[2];
    const float* qkv_w  = (const float*)d_in[3];
    const float* qkv_b  = (const float*)d_in[4];
    const float* proj_w = (const float*)d_in[5];
    const float* proj_b = (const float*)d_in[6];
    const float* ln2_w  = (const float*)d_in[7];
    const float* ln2_b  = (const float*)d_in[8];
    const float* mlp_w1 = (const float*)d_in[9];
    const float* mlp_b1 = (const float*)d_in[10];
    const float* mlp_w2 = (const float*)d_in[11];
    const float* mlp_b2 = (const float*)d_in[12];
    float* out = (float*)d_out;

    float *px;
    __half *py, *pa, *ph, *pq, *pk, *pv;
    __half *wq, *wp, *w1, *w2;
    cudaGetSymbolAddress((void**)&px, g_x);
    cudaGetSymbolAddress((void**)&py, g_y);
    cudaGetSymbolAddress((void**)&pa, g_a);
    cudaGetSymbolAddress((void**)&ph, g_h);
    cudaGetSymbolAddress((void**)&pq, g_q);
    cudaGetSymbolAddress((void**)&pk, g_k);
    cudaGetSymbolAddress((void**)&pv, g_v);
    cudaGetSymbolAddress((void**)&wq, g_wq);
    cudaGetSymbolAddress((void**)&wp, g_wp);
    cudaGetSymbolAddress((void**)&w1, g_w1);
    cudaGetSymbolAddress((void**)&w2, g_w2);

    const int SMEMSZ  = 3 * (128 * 80 + 64 * 80);      // 46080 B (gemm, 3 stages)
    const int FSMEMSZ = 128 * 144 + 2 * 2 * 64 * 144;  // 55296 B (flash)
    cudaFuncSetAttribute(gemm_mma<2>, cudaFuncAttributeMaxDynamicSharedMemorySize, SMEMSZ);
    cudaFuncSetAttribute(gemm_mma<3>, cudaFuncAttributeMaxDynamicSharedMemorySize, SMEMSZ);
    cudaFuncSetAttribute(gemm_mma<4>, cudaFuncAttributeMaxDynamicSharedMemorySize, SMEMSZ);
    cudaFuncSetAttribute(flash_kernel, cudaFuncAttributeMaxDynamicSharedMemorySize, FSMEMSZ);

    // weight transpose to fp16
    dim3 blk(32, 8);
    wconvert<<<dim3(3 * DIM / 32, DIM / 32, DEPTH), blk>>>(qkv_w,  wq, DIM,  3 * DIM);
    wconvert<<<dim3(DIM / 32,     DIM / 32, DEPTH), blk>>>(proj_w, wp, DIM,  DIM);
    wconvert<<<dim3(MLPD / 32,    DIM / 32, DEPTH), blk>>>(mlp_w1, w1, DIM,  MLPD);
    wconvert<<<dim3(DIM / 32,    MLPD / 32, DEPTH), blk>>>(mlp_w2, w2, MLPD, DIM);

    for (int l = 0; l < DEPTH; l++) {
        size_t oq = (size_t)l * 3 * DIM * DIM;
        size_t op = (size_t)l * DIM * DIM;
        size_t o1 = (size_t)l * MLPD * DIM;
        size_t o2 = (size_t)l * DIM * MLPD;
        const float* xcur = (l == 0) ? x_in : px;
        float* xnext = (l == DEPTH - 1) ? out : px;

        // ---- attention sublayer ----
        ln_half<<<TOK / 8, 256>>>(xcur, ln1_w + (size_t)l * DIM, ln1_b + (size_t)l * DIM, py);
        gemm_mma<4><<<dim3(3 * DIM / 64, TOK / 128), 256, SMEMSZ>>>(
            py, wq + oq, qkv_b + (size_t)l * 3 * DIM, nullptr,
            nullptr, nullptr, pq, pk, pv, TOK, 3 * DIM, DIM);
        flash_kernel<<<dim3(8, BATCH * HEADS), 256, FSMEMSZ>>>(pq, pk, pv, pa);
        gemm_mma<3><<<dim3(DIM / 64, TOK / 128), 256, SMEMSZ>>>(
            pa, wp + op, proj_b + (size_t)l * DIM, xcur,
            px, nullptr, nullptr, nullptr, nullptr, TOK, DIM, DIM);

        // ---- MLP sublayer ----
        ln_half<<<TOK / 8, 256>>>(px, ln2_w + (size_t)l * DIM, ln2_b + (size_t)l * DIM, py);
        gemm_mma<2><<<dim3(MLPD / 64, TOK / 128), 256, SMEMSZ>>>(
            py, w1 + o1, mlp_b1 + (size_t)l * MLPD, nullptr,
            nullptr, ph, nullptr, nullptr, nullptr, TOK, MLPD, DIM);
        gemm_mma<3><<<dim3(DIM / 64, TOK / 128), 256, SMEMSZ>>>(
            ph, w2 + o2, mlp_b2 + (size_t)l * DIM, px,
            xnext, nullptr, nullptr, nullptr, nullptr, TOK, DIM, MLPD);
    }
}

// round 16
// speedup vs baseline: 1.0892x; 1.0892x over previous
#include <cuda_runtime.h>
#include <cuda_bf16.h>
#include <cuda_fp16.h>
#include <math.h>
#include <stdint.h>

// ----------------------------------------------------------------------------
// Transformer forward: 6 layers, B=4, N=1024, D=1024, H=16, hd=64, MLP=4096
// Round 15: R9 proven kernels + 2 CTAs/SM on dense GEMMs (epilogue/prologue
// overlap via co-residency). No PDL (container-failed under graph capture).
// Numerics identical to R9.
// ----------------------------------------------------------------------------

static constexpr int BATCH  = 4;
static constexpr int SEQ    = 1024;
static constexpr int DIM    = 1024;
static constexpr int HEADS  = 16;
static constexpr int HD     = 64;
static constexpr int MLPD   = 4096;
static constexpr int DEPTH  = 6;
static constexpr int TOK    = BATCH * SEQ;          // 4096
static constexpr float EPS  = 1e-5f;
static constexpr float SCALE = 0.03125f;            // DIM^-0.5

// ---------------- scratch (device globals; no allocation) -------------------
__device__ float  g_x [(size_t)TOK * DIM];
__device__ __half g_y [(size_t)TOK * DIM];   // LN out
__device__ __half g_q [(size_t)TOK * DIM];   // [bh][n][64]
__device__ __half g_k [(size_t)TOK * DIM];
__device__ __half g_v [(size_t)TOK * DIM];
__device__ __half g_a [(size_t)TOK * DIM];   // attn out [tok][DIM]
__device__ __half g_h [(size_t)TOK * MLPD];  // MLP hidden

// transposed fp16 weights
__device__ __half g_wq[(size_t)DEPTH * 3 * DIM * DIM];
__device__ __half g_wp[(size_t)DEPTH * DIM * DIM];
__device__ __half g_w1[(size_t)DEPTH * MLPD * DIM];
__device__ __half g_w2[(size_t)DEPTH * DIM * MLPD];

// ---------------------------- PTX helpers -----------------------------------
__device__ __forceinline__ uint32_t smem_u32(const void* p) {
    uint32_t a;
    asm("{ .reg .u64 t; cvta.to.shared.u64 t, %1; cvt.u32.u64 %0, t; }"
        : "=r"(a) : "l"(p));
    return a;
}

__device__ __forceinline__ void ldsm4(uint32_t* r, uint32_t a) {
    asm volatile("ldmatrix.sync.aligned.m8n8.x4.shared.b16 {%0,%1,%2,%3}, [%4];"
        : "=r"(r[0]), "=r"(r[1]), "=r"(r[2]), "=r"(r[3]) : "r"(a));
}
__device__ __forceinline__ void ldsm4t(uint32_t* r, uint32_t a) {
    asm volatile("ldmatrix.sync.aligned.m8n8.x4.trans.shared.b16 {%0,%1,%2,%3}, [%4];"
        : "=r"(r[0]), "=r"(r[1]), "=r"(r[2]), "=r"(r[3]) : "r"(a));
}

__device__ __forceinline__ void mma_h(float* c, const uint32_t* a,
                                      uint32_t b0, uint32_t b1) {
    asm volatile("mma.sync.aligned.m16n8k16.row.col.f32.f16.f16.f32 "
        "{%0,%1,%2,%3}, {%4,%5,%6,%7}, {%8,%9}, {%0,%1,%2,%3};"
        : "+f"(c[0]), "+f"(c[1]), "+f"(c[2]), "+f"(c[3])
        : "r"(a[0]), "r"(a[1]), "r"(a[2]), "r"(a[3]), "r"(b0), "r"(b1));
}

#define CP_ASYNC16(saddr, gptr) \
    asm volatile("cp.async.cg.shared.global [%0], [%1], 16;" :: "r"(saddr), "l"(gptr))
#define CP_COMMIT() asm volatile("cp.async.commit_group;" ::: "memory")
#define CP_WAIT(n)  asm volatile("cp.async.wait_group %0;" :: "n"(n) : "memory")

__device__ __forceinline__ uint32_t packh2(float x, float y) {
    __half2 p = __floats2half2_rn(x, y);
    return *(uint32_t*)&p;
}

// ----------------------------------------------------------------------------
// Weight transpose to fp16: W [L,K,N] fp32 -> Wt [L,N,K] fp16
__global__ void wconvert(const float* __restrict__ W, __half* __restrict__ Th,
                         int K, int N) {
    __shared__ float t[32][33];
    size_t loff = (size_t)blockIdx.z * K * N;
    const float* Wl = W + loff;
    int n0 = blockIdx.x * 32, k0 = blockIdx.y * 32;
    #pragma unroll
    for (int i = 0; i < 4; i++) {
        int k = k0 + threadIdx.y + i * 8;
        t[threadIdx.y + i * 8][threadIdx.x] = Wl[(size_t)k * N + n0 + threadIdx.x];
    }
    __syncthreads();
    #pragma unroll
    for (int i = 0; i < 4; i++) {
        int n = n0 + threadIdx.y + i * 8;
        float v = t[threadIdx.x][threadIdx.y + i * 8];
        Th[loff + (size_t)n * K + k0 + threadIdx.x] = __float2half_rn(v);
    }
}

// ----------------------------------------------------------------------------
// LayerNorm: warp per row, one pass (sum + sumsq), fp16 output.
__global__ void ln_half(const float* __restrict__ x,
                        const float* __restrict__ w,
                        const float* __restrict__ b,
                        __half* __restrict__ y) {
    int row = blockIdx.x * 8 + (threadIdx.x >> 5);
    int lane = threadIdx.x & 31;
    const float4* xr = (const float4*)(x + (size_t)row * DIM);
    const float4* w4 = (const float4*)w;
    const float4* b4 = (const float4*)b;

    float4 v[8];
    float s = 0.f, s2 = 0.f;
    #pragma unroll
    for (int i = 0; i < 8; i++) {
        v[i] = xr[lane + i * 32];
        s  += v[i].x + v[i].y + v[i].z + v[i].w;
        s2 += v[i].x * v[i].x + v[i].y * v[i].y + v[i].z * v[i].z + v[i].w * v[i].w;
    }
    #pragma unroll
    for (int o = 16; o > 0; o >>= 1) {
        s  += __shfl_xor_sync(0xffffffffu, s,  o);
        s2 += __shfl_xor_sync(0xffffffffu, s2, o);
    }
    float mu = s * (1.0f / DIM);
    float var = s2 * (1.0f / DIM) - mu * mu;
    float rstd = rsqrtf(var + EPS);

    __half* yr = y + (size_t)row * DIM;
    #pragma unroll
    for (int i = 0; i < 8; i++) {
        int idx = (lane + i * 32);
        float4 wv = w4[idx], bv = b4[idx];
        float g0 = (v[i].x - mu) * rstd * wv.x + bv.x;
        float g1 = (v[i].y - mu) * rstd * wv.y + bv.y;
        float g2 = (v[i].z - mu) * rstd * wv.z + bv.z;
        float g3 = (v[i].w - mu) * rstd * wv.w + bv.w;
        uint2 pk;
        pk.x = packh2(g0, g1);
        pk.y = packh2(g2, g3);
        *(uint2*)(yr + idx * 4) = pk;
    }
}

// ----------------------------------------------------------------------------
// Dense GEMM, single-product fp16: C = A @ B (fp32 accum)
// CTA tile 128x128, BK=32, 8 warps (2m x 4n), 3-stage cp.async, 2 CTAs/SM.
// EPI: 2 = +bias,gelu -> fp16 Ch;  3 = +bias+res -> fp32 Cf;
//      4 = +bias -> scatter fp16 QKV (per-head layout)
template<int EPI>
__global__ void __launch_bounds__(256, 2)
gemm_mma(const __half* __restrict__ A, const __half* __restrict__ B,
         const float* __restrict__ bias, const float* __restrict__ res,
         float* __restrict__ Cf, __half* __restrict__ Ch,
         __half* __restrict__ Qp, __half* __restrict__ Kp, __half* __restrict__ Vp,
         int M, int N, int K) {
    constexpr int STAGES = 3;
    constexpr int ROWB   = 80;
    constexpr int TILEB  = 128 * ROWB;    // 10240 B per operand tile
    constexpr int STAGEB = 2 * TILEB;     // 20480 B per stage

    extern __shared__ char smem[];
    uint32_t sb = smem_u32(smem);
    int tid = threadIdx.x, lane = tid & 31, wid = tid >> 5;
    int bm = blockIdx.y * 128, bn = blockIdx.x * 128;
    int warp_m = wid >> 2, warp_n = wid & 3;

    const __half* srcs[2] = { A + (size_t)bm * K, B + (size_t)bn * K };
    int nch = K >> 5;

    int g = lane >> 3;
    uint32_t rowsel = (uint32_t)(((g & 1) << 3) + (lane & 7));
    uint32_t colsel = (uint32_t)((g >> 1) * 16);

    float acc[4][4][4];
    #pragma unroll
    for (int i = 0; i < 4; i++)
        #pragma unroll
        for (int j = 0; j < 4; j++)
            #pragma unroll
            for (int q = 0; q < 4; q++) acc[i][j][q] = 0.f;

    auto issue = [&](int ch) {
        int k0 = ch << 5;
        uint32_t sbase = sb + (uint32_t)(ch % STAGES) * STAGEB;
        #pragma unroll
        for (int j = 0; j < 4; j++) {
            int c2 = j * 256 + tid;
            int op = c2 >> 9, idx = c2 & 511, row = idx >> 2, ck = idx & 3;
            const __half* gp = srcs[op] + (size_t)row * K + k0 + ck * 8;
            uint32_t sa = sbase + (uint32_t)(op * TILEB + row * ROWB + ck * 16);
            CP_ASYNC16(sa, gp);
        }
    };

    #pragma unroll
    for (int s = 0; s < STAGES; s++) { issue(s); CP_COMMIT(); }

    for (int c = 0; c < nch; c++) {
        CP_WAIT(STAGES - 1);
        __syncthreads();
        uint32_t st = sb + (uint32_t)((c % STAGES) * STAGEB);

        #pragma unroll
        for (int kh2 = 0; kh2 < 2; kh2++) {
            uint32_t kb = (uint32_t)(kh2 * 32) + colsel;
            uint32_t af[4][4], bf[2][4];
            #pragma unroll
            for (int mi = 0; mi < 4; mi++) {
                uint32_t r = (uint32_t)(warp_m * 64 + mi * 16) + rowsel;
                ldsm4(af[mi], st + r * ROWB + kb);
            }
            #pragma unroll
            for (int ni = 0; ni < 2; ni++) {
                uint32_t r = (uint32_t)(warp_n * 32 + ni * 16) + rowsel;
                ldsm4(bf[ni], st + TILEB + r * ROWB + kb);
            }
            #pragma unroll
            for (int mi = 0; mi < 4; mi++)
                #pragma unroll
                for (int nj = 0; nj < 4; nj++)
                    mma_h(acc[mi][nj], af[mi], bf[nj >> 1][nj & 1], bf[nj >> 1][(nj & 1) + 2]);
        }
        __syncthreads();
        if (c + STAGES < nch) issue(c + STAGES);
        CP_COMMIT();
    }

    // ---- epilogue ----
    #pragma unroll
    for (int mi = 0; mi < 4; mi++) {
        int r0 = bm + warp_m * 64 + mi * 16 + (lane >> 2);
        #pragma unroll
        for (int nj = 0; nj < 4; nj++) {
            int cc = bn + warp_n * 32 + nj * 8 + (lane & 3) * 2;
            float b0 = bias[cc], b1 = bias[cc + 1];
            #pragma unroll
            for (int half = 0; half < 2; half++) {
                int r = r0 + half * 8;
                float v0 = acc[mi][nj][half * 2 + 0] + b0;
                float v1 = acc[mi][nj][half * 2 + 1] + b1;
                if (EPI == 2) {
                    size_t o = (size_t)r * N + cc;
                    v0 = 0.5f * v0 * (1.0f + erff(v0 * 0.70710678118654752f));
                    v1 = 0.5f * v1 * (1.0f + erff(v1 * 0.70710678118654752f));
                    *(uint32_t*)(Ch + o) = packh2(v0, v1);
                } else if (EPI == 3) {
                    size_t o = (size_t)r * N + cc;
                    v0 += res[o];
                    v1 += res[o + 1];
                    float2 f2; f2.x = v0; f2.y = v1;
                    *(float2*)(Cf + o) = f2;
                } else {  // EPI == 4: scatter qkv -> per-head fp16 layout
                    int sel = cc >> 10, hh = (cc >> 6) & 15, d = cc & 63;
                    int bb = r >> 10, nn = r & 1023;
                    size_t o = ((size_t)((bb << 4) + hh) * SEQ + nn) * 64 + d;
                    __half* dh = (sel == 0) ? Qp : (sel == 1) ? Kp : Vp;
                    *(uint32_t*)(dh + o) = packh2(v0, v1);
                }
            }
        }
    }
}

// ----------------------------------------------------------------------------
// Fused flash attention, single-product fp16 (unchanged from R9).
__global__ void __launch_bounds__(256, 1)
flash_kernel(const __half* __restrict__ Q, const __half* __restrict__ K,
             const __half* __restrict__ V, __half* __restrict__ O) {
    constexpr int RSTR   = 144;
    constexpr int KVT    = 64 * RSTR;
    constexpr int STAGEB = 2 * KVT;
    constexpr int QB     = 128 * RSTR;

    extern __shared__ char smem[];
    uint32_t sb = smem_u32(smem);
    int tid = threadIdx.x, lane = tid & 31, wid = tid >> 5;
    int bh = blockIdx.y, i0 = blockIdx.x * 128;
    size_t seqb = (size_t)bh * SEQ * 64;

    {
        const __half* qsrc = Q + seqb + (size_t)i0 * 64;
        #pragma unroll
        for (int j = 0; j < 4; j++) {
            int idx = j * 256 + tid;
            int row = idx >> 3, ck = idx & 7;
            CP_ASYNC16(sb + (uint32_t)(row * RSTR + ck * 16),
                       qsrc + (size_t)row * 64 + ck * 8);
        }
        CP_COMMIT();
    }
    const __half* kvs[2] = { K + seqb, V + seqb };
    auto issueKV = [&](int it) {
        int k0 = it * 64;
        uint32_t base = sb + QB + (uint32_t)(it & 1) * STAGEB;
        #pragma unroll
        for (int j = 0; j < 4; j++) {
            int idx = j * 256 + tid;
            int op = idx >> 9, rem = idx & 511, row = rem >> 3, ck = rem & 7;
            CP_ASYNC16(base + (uint32_t)(op * KVT + row * RSTR + ck * 16),
                       kvs[op] + (size_t)(k0 + row) * 64 + ck * 8);
        }
    };
    issueKV(0); CP_COMMIT();
    issueKV(1); CP_COMMIT();

    int g = lane >> 3;
    uint32_t lrow = (uint32_t)(((g & 1) << 3) + (lane & 7));
    uint32_t lcol = (uint32_t)((g >> 1) * 16);

    CP_WAIT(2);
    __syncthreads();
    uint32_t qf[4][4];
    {
        int r0 = wid * 16;
        #pragma unroll
        for (int c = 0; c < 4; c++)
            ldsm4(qf[c], sb + (uint32_t)((r0 + lrow) * RSTR + c * 32) + lcol);
    }

    float m0 = -1e30f, m1 = -1e30f, l0 = 0.f, l1 = 0.f;
    float o[8][4];
    #pragma unroll
    for (int nb = 0; nb < 8; nb++)
        #pragma unroll
        for (int q = 0; q < 4; q++) o[nb][q] = 0.f;

    for (int it = 0; it < 16; it++) {
        CP_WAIT(1);
        __syncthreads();
        uint32_t st = sb + QB + (uint32_t)(it & 1) * STAGEB;

        float s[8][4];
        #pragma unroll
        for (int nb = 0; nb < 8; nb++)
            #pragma unroll
            for (int q = 0; q < 4; q++) s[nb][q] = 0.f;

        #pragma unroll
        for (int c = 0; c < 4; c++) {
            uint32_t kf[4][4];
            #pragma unroll
            for (int p = 0; p < 4; p++)
                ldsm4(kf[p], st + (uint32_t)((p * 16 + lrow) * RSTR + c * 32) + lcol);
            #pragma unroll
            for (int p = 0; p < 4; p++) {
                mma_h(s[2 * p],     qf[c], kf[p][0], kf[p][2]);
                mma_h(s[2 * p + 1], qf[c], kf[p][1], kf[p][3]);
            }
        }

        float rm0 = -1e30f, rm1 = -1e30f;
        #pragma unroll
        for (int nb = 0; nb < 8; nb++) {
            #pragma unroll
            for (int q = 0; q < 4; q++) s[nb][q] *= SCALE;
            rm0 = fmaxf(rm0, fmaxf(s[nb][0], s[nb][1]));
            rm1 = fmaxf(rm1, fmaxf(s[nb][2], s[nb][3]));
        }
        rm0 = fmaxf(rm0, __shfl_xor_sync(0xffffffffu, rm0, 1));
        rm0 = fmaxf(rm0, __shfl_xor_sync(0xffffffffu, rm0, 2));
        rm1 = fmaxf(rm1, __shfl_xor_sync(0xffffffffu, rm1, 1));
        rm1 = fmaxf(rm1, __shfl_xor_sync(0xffffffffu, rm1, 2));
        float nm0 = fmaxf(m0, rm0), nm1 = fmaxf(m1, rm1);
        float a0 = __expf(m0 - nm0), a1 = __expf(m1 - nm1);
        m0 = nm0; m1 = nm1;

        float sum0 = 0.f, sum1 = 0.f;
        uint32_t pf[4][4];
        #pragma unroll
        for (int nb = 0; nb < 8; nb++) {
            float p00 = __expf(s[nb][0] - nm0);
            float p01 = __expf(s[nb][1] - nm0);
            float p10 = __expf(s[nb][2] - nm1);
            float p11 = __expf(s[nb][3] - nm1);
            sum0 += p00 + p01;
            sum1 += p10 + p11;
            int c = nb >> 1, off = (nb & 1) ? 2 : 0;
            pf[c][off + 0] = packh2(p00, p01);
            pf[c][off + 1] = packh2(p10, p11);
        }
        sum0 += __shfl_xor_sync(0xffffffffu, sum0, 1);
        sum0 += __shfl_xor_sync(0xffffffffu, sum0, 2);
        sum1 += __shfl_xor_sync(0xffffffffu, sum1, 1);
        sum1 += __shfl_xor_sync(0xffffffffu, sum1, 2);
        l0 = l0 * a0 + sum0;
        l1 = l1 * a1 + sum1;
        #pragma unroll
        for (int nb = 0; nb < 8; nb++) {
            o[nb][0] *= a0; o[nb][1] *= a0;
            o[nb][2] *= a1; o[nb][3] *= a1;
        }

        #pragma unroll
        for (int c = 0; c < 4; c++) {
            uint32_t vf[4][4];
            #pragma unroll
            for (int dp = 0; dp < 4; dp++)
                ldsm4t(vf[dp], st + KVT + (uint32_t)((c * 16 + lrow) * RSTR + dp * 32) + lcol);
            #pragma unroll
            for (int dp = 0; dp < 4; dp++) {
                mma_h(o[2 * dp],     pf[c], vf[dp][0], vf[dp][1]);
                mma_h(o[2 * dp + 1], pf[c], vf[dp][2], vf[dp][3]);
            }
        }
        __syncthreads();
        if (it + 2 < 16) issueKV(it + 2);
        CP_COMMIT();
    }

    float inv0 = 1.0f / l0, inv1 = 1.0f / l1;
    int b = bh >> 4, h = bh & 15;
    int nrow = i0 + wid * 16 + (lane >> 2);
    size_t t0 = (size_t)b * SEQ + nrow;
    #pragma unroll
    for (int nb = 0; nb < 8; nb++) {
        int col = h * 64 + nb * 8 + (lane & 3) * 2;
        *(uint32_t*)(O + t0 * DIM + col)       = packh2(o[nb][0] * inv0, o[nb][1] * inv0);
        *(uint32_t*)(O + (t0 + 8) * DIM + col) = packh2(o[nb][2] * inv1, o[nb][3] * inv1);
    }
}

// ----------------------------------------------------------------------------
extern "C" void kernel_launch(void* const* d_in, const int* in_sizes, int n_in,
                              void* d_out, int out_size) {
    const float* x_in   = (const float*)d_in[0];
    const float* ln1_w  = (const float*)d_in[1];
    const float* ln1_b  = (const float*)d_in[2];
    const float* qkv_w  = (const float*)d_in[3];
    const float* qkv_b  = (const float*)d_in[4];
    const float* proj_w = (const float*)d_in[5];
    const float* proj_b = (const float*)d_in[6];
    const float* ln2_w  = (const float*)d_in[7];
    const float* ln2_b  = (const float*)d_in[8];
    const float* mlp_w1 = (const float*)d_in[9];
    const float* mlp_b1 = (const float*)d_in[10];
    const float* mlp_w2 = (const float*)d_in[11];
    const float* mlp_b2 = (const float*)d_in[12];
    float* out = (float*)d_out;

    float *px;
    __half *py, *pa, *ph, *pq, *pk, *pv;
    __half *wq, *wp, *w1, *w2;
    cudaGetSymbolAddress((void**)&px, g_x);
    cudaGetSymbolAddress((void**)&py, g_y);
    cudaGetSymbolAddress((void**)&pa, g_a);
    cudaGetSymbolAddress((void**)&ph, g_h);
    cudaGetSymbolAddress((void**)&pq, g_q);
    cudaGetSymbolAddress((void**)&pk, g_k);
    cudaGetSymbolAddress((void**)&pv, g_v);
    cudaGetSymbolAddress((void**)&wq, g_wq);
    cudaGetSymbolAddress((void**)&wp, g_wp);
    cudaGetSymbolAddress((void**)&w1, g_w1);
    cudaGetSymbolAddress((void**)&w2, g_w2);

    const int SMEMSZ  = 3 * 2 * 128 * 80;              // 61440 B (gemm)
    const int FSMEMSZ = 128 * 144 + 2 * 2 * 64 * 144;  // 55296 B (flash)
    cudaFuncSetAttribute(gemm_mma<2>, cudaFuncAttributeMaxDynamicSharedMemorySize, SMEMSZ);
    cudaFuncSetAttribute(gemm_mma<3>, cudaFuncAttributeMaxDynamicSharedMemorySize, SMEMSZ);
    cudaFuncSetAttribute(gemm_mma<4>, cudaFuncAttributeMaxDynamicSharedMemorySize, SMEMSZ);
    cudaFuncSetAttribute(flash_kernel, cudaFuncAttributeMaxDynamicSharedMemorySize, FSMEMSZ);

    // weight transpose to fp16
    dim3 blk(32, 8);
    wconvert<<<dim3(3 * DIM / 32, DIM / 32, DEPTH), blk>>>(qkv_w,  wq, DIM,  3 * DIM);
    wconvert<<<dim3(DIM / 32,     DIM / 32, DEPTH), blk>>>(proj_w, wp, DIM,  DIM);
    wconvert<<<dim3(MLPD / 32,    DIM / 32, DEPTH), blk>>>(mlp_w1, w1, DIM,  MLPD);
    wconvert<<<dim3(DIM / 32,    MLPD / 32, DEPTH), blk>>>(mlp_w2, w2, MLPD, DIM);

    for (int l = 0; l < DEPTH; l++) {
        size_t oq = (size_t)l * 3 * DIM * DIM;
        size_t op = (size_t)l * DIM * DIM;
        size_t o1 = (size_t)l * MLPD * DIM;
        size_t o2 = (size_t)l * DIM * MLPD;
        const float* xcur = (l == 0) ? x_in : px;
        float* xnext = (l == DEPTH - 1) ? out : px;

        // ---- attention sublayer ----
        ln_half<<<TOK / 8, 256>>>(xcur, ln1_w + (size_t)l * DIM, ln1_b + (size_t)l * DIM, py);
        gemm_mma<4><<<dim3(3 * DIM / 128, TOK / 128), 256, SMEMSZ>>>(
            py, wq + oq, qkv_b + (size_t)l * 3 * DIM, nullptr,
            nullptr, nullptr, pq, pk, pv, TOK, 3 * DIM, DIM);
        flash_kernel<<<dim3(8, BATCH * HEADS), 256, FSMEMSZ>>>(pq, pk, pv, pa);
        gemm_mma<3><<<dim3(DIM / 128, TOK / 128), 256, SMEMSZ>>>(
            pa, wp + op, proj_b + (size_t)l * DIM, xcur,
            px, nullptr, nullptr, nullptr, nullptr, TOK, DIM, DIM);

        // ---- MLP sublayer ----
        ln_half<<<TOK / 8, 256>>>(px, ln2_w + (size_t)l * DIM, ln2_b + (size_t)l * DIM, py);
        gemm_mma<2><<<dim3(MLPD / 128, TOK / 128), 256, SMEMSZ>>>(
            py, w1 + o1, mlp_b1 + (size_t)l * MLPD, nullptr,
            nullptr, ph, nullptr, nullptr, nullptr, TOK, MLPD, DIM);
        gemm_mma<3><<<dim3(DIM / 128, TOK / 128), 256, SMEMSZ>>>(
            ph, w2 + o2, mlp_b2 + (size_t)l * DIM, px,
            xnext, nullptr, nullptr, nullptr, nullptr, TOK, DIM, MLPD);
    }
}